// round 9
// baseline (speedup 1.0000x reference)
#include <cuda_runtime.h>
#include <cuda_fp16.h>
#include <math.h>
#include <stdint.h>

// Problem constants
#define Bc   16
#define NHc  16
#define DIMc 512
#define Lc   2304          // 48*48
#define NWc  64            // (48/6)^2
#define HID  2048          // 4*DIM
#define SCALEc 0.17677669529663689f   // 32^-0.5
#define NTOK (Bc*Lc)       // 36864
#define NKVQ 1536          // fused kv(1024) + q(512)

// ---------------- scratch (device globals; no allocation allowed) ----------
__device__ __half g_xnh [NTOK * DIMc];     // LN output in fp16 (GEMM A operand)
__device__ __half g_kvqh[NTOK * NKVQ];     // cols 0..511 k, 512..1023 v, 1024..1535 q
__device__ float  g_x1  [NTOK * DIMc];
__device__ __half g_h   [NTOK * HID];      // MLP hidden (fp16, A of fc2)
__device__ float  g_kvqavg[Bc * NKVQ];
__device__ float  g_xavgn[Bc * DIMc];
__device__ float  g_xavg1[Bc * DIMc];
__device__ float  g_havg [Bc * HID];
// transposed ([N,K] row-major) fp16 weights
__device__ __half g_wkvqT[NKVQ * DIMc];
__device__ float  g_bkvq [NKVQ];
__device__ __half g_wfc1T[HID * DIMc];
__device__ __half g_wfc2T[DIMc * HID];

__device__ __forceinline__ float gelu_exact(float v) {
    return 0.5f * v * (1.0f + erff(v * 0.70710678118654752440f));
}

#define CP16(dst, src) \
    asm volatile("cp.async.cg.shared.global [%0], [%1], 16;\n" :: "r"(dst), "l"(src))
#define CPCOMMIT() asm volatile("cp.async.commit_group;\n")
#define LDSM4(r0, r1, r2, r3, addr) \
    asm volatile("ldmatrix.sync.aligned.m8n8.x4.shared.b16 {%0,%1,%2,%3}, [%4];" \
                 : "=r"(r0), "=r"(r1), "=r"(r2), "=r"(r3) : "r"(addr))

// ---------------- weight prep: tiled transpose + fp16 convert --------------
__global__ __launch_bounds__(256)
void transpose_half(const float* __restrict__ src, __half* __restrict__ dst,
                    int K, int N)
{
    __shared__ float tile[32][33];
    const int kb = blockIdx.y * 32, nb = blockIdx.x * 32;
    const int tx = threadIdx.x, ty = threadIdx.y;
    #pragma unroll
    for (int i = ty; i < 32; i += 8)
        tile[i][tx] = src[(size_t)(kb + i) * N + nb + tx];
    __syncthreads();
    #pragma unroll
    for (int i = ty; i < 32; i += 8)
        dst[(size_t)(nb + i) * K + kb + tx] = __float2half_rn(tile[tx][i]);
}

__global__ void fuse_bias(const float* __restrict__ b_kv, const float* __restrict__ b_q,
                          float* __restrict__ bkvq)
{
    const int i = blockIdx.x * blockDim.x + threadIdx.x;
    if (i < NKVQ) bkvq[i] = (i < 2 * DIMc) ? b_kv[i] : b_q[i - 2 * DIMc];
}

// ---------------- LayerNorm over DIM=512, one block per token --------------
__global__ __launch_bounds__(128)
void ln_kernel_f(const float* __restrict__ x, const float* __restrict__ g,
                 const float* __restrict__ be, float* __restrict__ y)
{
    __shared__ float sS[4], sQ[4];
    const int t = blockIdx.x;
    const int tid = threadIdx.x;
    const float4 v = ((const float4*)(x + (size_t)t * DIMc))[tid];
    float s = v.x + v.y + v.z + v.w;
    float q = v.x*v.x + v.y*v.y + v.z*v.z + v.w*v.w;
    #pragma unroll
    for (int o = 16; o; o >>= 1) {
        s += __shfl_xor_sync(0xffffffffu, s, o);
        q += __shfl_xor_sync(0xffffffffu, q, o);
    }
    if ((tid & 31) == 0) { sS[tid >> 5] = s; sQ[tid >> 5] = q; }
    __syncthreads();
    const float S = sS[0] + sS[1] + sS[2] + sS[3];
    const float Q = sQ[0] + sQ[1] + sQ[2] + sQ[3];
    const float mean = S * (1.0f / 512.0f);
    const float var  = Q * (1.0f / 512.0f) - mean * mean;
    const float rstd = rsqrtf(var + 1e-3f);
    const float4 gg = ((const float4*)g)[tid];
    const float4 bb = ((const float4*)be)[tid];
    float4 o;
    o.x = (v.x - mean) * rstd * gg.x + bb.x;
    o.y = (v.y - mean) * rstd * gg.y + bb.y;
    o.z = (v.z - mean) * rstd * gg.z + bb.z;
    o.w = (v.w - mean) * rstd * gg.w + bb.w;
    ((float4*)(y + (size_t)t * DIMc))[tid] = o;
}

__global__ __launch_bounds__(128)
void ln_kernel_h(const float* __restrict__ x, const float* __restrict__ g,
                 const float* __restrict__ be, __half* __restrict__ y)
{
    __shared__ float sS[4], sQ[4];
    const int t = blockIdx.x;
    const int tid = threadIdx.x;
    const float4 v = ((const float4*)(x + (size_t)t * DIMc))[tid];
    float s = v.x + v.y + v.z + v.w;
    float q = v.x*v.x + v.y*v.y + v.z*v.z + v.w*v.w;
    #pragma unroll
    for (int o = 16; o; o >>= 1) {
        s += __shfl_xor_sync(0xffffffffu, s, o);
        q += __shfl_xor_sync(0xffffffffu, q, o);
    }
    if ((tid & 31) == 0) { sS[tid >> 5] = s; sQ[tid >> 5] = q; }
    __syncthreads();
    const float S = sS[0] + sS[1] + sS[2] + sS[3];
    const float Q = sQ[0] + sQ[1] + sQ[2] + sQ[3];
    const float mean = S * (1.0f / 512.0f);
    const float var  = Q * (1.0f / 512.0f) - mean * mean;
    const float rstd = rsqrtf(var + 1e-3f);
    const float4 gg = ((const float4*)g)[tid];
    const float4 bb = ((const float4*)be)[tid];
    __half2 h0 = __floats2half2_rn((v.x - mean) * rstd * gg.x + bb.x,
                                   (v.y - mean) * rstd * gg.y + bb.y);
    __half2 h1 = __floats2half2_rn((v.z - mean) * rstd * gg.z + bb.z,
                                   (v.w - mean) * rstd * gg.w + bb.w);
    __half2* yp = (__half2*)(y + (size_t)t * DIMc);
    yp[tid * 2 + 0] = h0;
    yp[tid * 2 + 1] = h1;
}

// ---------------- fp16 tensor-core GEMM: 128x256 tile, 64x64/warp ----------
// C[M,N] = act(A[M,K]h @ WT[N,K]h^T + bias)(+R). 256 threads, 2x4 warps of
// 64x64, mma.m16n8k16.f16.f32, LDSM fragments, 4-stage cp.async pipeline in
// dynamic smem.
template<int ACT, bool RES, bool OUTH>
__global__ __launch_bounds__(256, 1)
void hgemm(int M, int N, int K,
           const __half* __restrict__ A, const __half* __restrict__ WT,
           const float* __restrict__ bias, const float* __restrict__ R,
           void* __restrict__ Cv)
{
    constexpr int BM = 128, BN = 256, BK = 32;   // BK in halfs
    constexpr int PAD = 40;                       // halfs per smem row
    constexpr int STG = 4;
    constexpr uint32_t A_BYTES  = (uint32_t)BM * PAD * 2u;          // 10240
    constexpr uint32_t ST_BYTES = (uint32_t)(BM + BN) * PAD * 2u;   // 30720

    extern __shared__ __align__(16) __half smem[];

    const int tid  = threadIdx.x;
    const int lane = tid & 31;
    const int warp = tid >> 5;
    const int wm   = warp >> 2;          // 0..1  (64-row group)
    const int wn   = warp & 3;           // 0..3  (64-col group)
    const int bm   = blockIdx.y * BM;
    const int bn   = blockIdx.x * BN;

    const uint32_t sb = (uint32_t)__cvta_generic_to_shared(smem);

    // ---- loaders ----
    // A tile: 128 rows x 64B; thread: row=tid>>1, 32B half -> 2 chunks
    const int a_r = tid >> 1;
    const int a_o = (tid & 1) << 4;      // half offset 0 or 16
    const __half* a_src = A + (size_t)(bm + a_r) * K + a_o;
    const uint32_t a_dst = sb + (uint32_t)(a_r * PAD + a_o) * 2u;
    // B tile: 256 rows x 64B; thread: row=tid -> 4 chunks
    const __half* b_src = WT + (size_t)(bn + tid) * K;
    const uint32_t b_dst = sb + A_BYTES + (uint32_t)(tid * PAD) * 2u;

    // ---- ldmatrix base addresses (stage 0) ----
    uint32_t aLd[4];
    #pragma unroll
    for (int mt = 0; mt < 4; mt++) {
        const int row = wm * 64 + mt * 16 + (lane & 15);
        const int col = (lane >> 4) * 8;
        aLd[mt] = sb + (uint32_t)(row * PAD + col) * 2u;
    }
    uint32_t bLd[4];
    #pragma unroll
    for (int ng = 0; ng < 4; ng++) {
        const int row = wn * 64 + ng * 16 + (lane & 7) + (lane >> 4) * 8;
        const int col = ((lane >> 3) & 1) * 8;
        bLd[ng] = sb + A_BYTES + (uint32_t)(row * PAD + col) * 2u;
    }

    float acc[4][8][4] = {};
    const int T = K / BK;

    // prologue: stages 0..STG-2
    #pragma unroll
    for (int s = 0; s < STG - 1; s++) {
        const uint32_t o = (uint32_t)s * ST_BYTES;
        const int k0 = s * BK;
        CP16(a_dst + o, a_src + k0); CP16(a_dst + o + 16u, a_src + k0 + 8);
        #pragma unroll
        for (int i = 0; i < 4; i++)
            CP16(b_dst + o + 16u * i, b_src + k0 + 8 * i);
        CPCOMMIT();
    }

    for (int t = 0; t < T; t++) {
        const int rem = T - 1 - t;
        if (rem >= 2)      { asm volatile("cp.async.wait_group 2;\n"); }
        else if (rem == 1) { asm volatile("cp.async.wait_group 1;\n"); }
        else               { asm volatile("cp.async.wait_group 0;\n"); }
        __syncthreads();

        // prefetch stage t+STG-1 into buffer (t+STG-1)%STG (freed by barrier)
        if (t + STG - 1 < T) {
            const int k0 = (t + STG - 1) * BK;
            const uint32_t o = (uint32_t)((t + STG - 1) % STG) * ST_BYTES;
            CP16(a_dst + o, a_src + k0); CP16(a_dst + o + 16u, a_src + k0 + 8);
            #pragma unroll
            for (int i = 0; i < 4; i++)
                CP16(b_dst + o + 16u * i, b_src + k0 + 8 * i);
            CPCOMMIT();
        }

        const uint32_t so = (uint32_t)(t % STG) * ST_BYTES;

        #pragma unroll
        for (int ks = 0; ks < BK; ks += 16) {
            uint32_t af[4][4];
            #pragma unroll
            for (int mt = 0; mt < 4; mt++)
                LDSM4(af[mt][0], af[mt][1], af[mt][2], af[mt][3],
                      aLd[mt] + so + (uint32_t)ks * 2u);
            uint32_t bf[8][2];
            #pragma unroll
            for (int ng = 0; ng < 4; ng++)
                LDSM4(bf[2*ng][0], bf[2*ng][1], bf[2*ng+1][0], bf[2*ng+1][1],
                      bLd[ng] + so + (uint32_t)ks * 2u);
            #pragma unroll
            for (int mt = 0; mt < 4; mt++)
                #pragma unroll
                for (int nt = 0; nt < 8; nt++)
                    asm volatile(
                        "mma.sync.aligned.m16n8k16.row.col.f32.f16.f16.f32 "
                        "{%0,%1,%2,%3}, {%4,%5,%6,%7}, {%8,%9}, {%0,%1,%2,%3};\n"
                        : "+f"(acc[mt][nt][0]), "+f"(acc[mt][nt][1]),
                          "+f"(acc[mt][nt][2]), "+f"(acc[mt][nt][3])
                        : "r"(af[mt][0]), "r"(af[mt][1]), "r"(af[mt][2]), "r"(af[mt][3]),
                          "r"(bf[nt][0]), "r"(bf[nt][1]));
        }
    }

    // ---- epilogue ----
    float* Cf = (float*)Cv;
    __half* Ch = (__half*)Cv;
    #pragma unroll
    for (int mt = 0; mt < 4; mt++) {
        #pragma unroll
        for (int nt = 0; nt < 8; nt++) {
            const int r0 = bm + wm * 64 + mt * 16 + (lane >> 2);
            const int c  = bn + wn * 64 + nt * 8 + (lane & 3) * 2;
            const float bx = bias[c], by = bias[c + 1];
            #pragma unroll
            for (int half_ = 0; half_ < 2; half_++) {
                const int r = r0 + half_ * 8;
                float vx = acc[mt][nt][half_ * 2 + 0] + bx;
                float vy = acc[mt][nt][half_ * 2 + 1] + by;
                if (ACT == 1) { vx = gelu_exact(vx); vy = gelu_exact(vy); }
                if (RES) {
                    const float2 rr = *(const float2*)(R + (size_t)r * N + c);
                    vx += rr.x; vy += rr.y;
                }
                if (OUTH) {
                    *(__half2*)(Ch + (size_t)r * N + c) = __floats2half2_rn(vx, vy);
                } else {
                    float2 o; o.x = vx; o.y = vy;
                    *(float2*)(Cf + (size_t)r * N + c) = o;
                }
            }
        }
    }
}

// ---------------- tiny GEMM for the 16 global tokens (fp32) ----------------
template<int ACT, bool RES>
__global__ __launch_bounds__(128)
void small_gemm(int N, int K, int ldC,
                const float* __restrict__ A, const float* __restrict__ W,
                const float* __restrict__ bias, const float* __restrict__ R,
                float* __restrict__ C)
{
    const int r = blockIdx.y;
    const int n = blockIdx.x * 128 + threadIdx.x;
    const float* a = A + (size_t)r * K;
    float acc = 0.0f;
    #pragma unroll 8
    for (int k = 0; k < K; k++)
        acc = fmaf(__ldg(a + k), W[(size_t)k * N + n], acc);
    float v = acc + bias[n];
    if (ACT == 1) v = gelu_exact(v);
    if (RES) v += R[(size_t)r * ldC + n];
    C[(size_t)r * ldC + n] = v;
}

// ---------------- window attention: one block per (window, head) -----------
__global__ __launch_bounds__(128)
void win_attn(const __half* __restrict__ kvq, const float* __restrict__ kvqavg,
              const float* __restrict__ table,
              const float* __restrict__ xin, float* __restrict__ x1)
{
    const int w = blockIdx.x;            // 0..1023
    const int h = blockIdx.y;            // 0..15
    const int b  = w >> 6;
    const int wi = w & 63;
    const int wr = wi >> 3, wc = wi & 7;

    __shared__ float qs[36][33];
    __shared__ float ks[37][33];
    __shared__ float vs[37][33];
    __shared__ float sc[36][37];

    const int tid = threadIdx.x;

    for (int idx = tid; idx < 36 * 32; idx += 128) {
        const int m = idx >> 5, d = idx & 31;
        const int r = m / 6, c = m % 6;
        const int l = (wr * 6 + r) * 48 + wc * 6 + c;
        const __half* row = kvq + (size_t)(b * Lc + l) * NKVQ + h * 32 + d;
        ks[m][d] = __half2float(row[0]);
        vs[m][d] = __half2float(row[DIMc]);
        qs[m][d] = __half2float(row[2 * DIMc]) * SCALEc;
    }
    if (tid < 32) {
        const float* row = kvqavg + (size_t)b * NKVQ + h * 32 + tid;
        ks[36][tid] = row[0];
        vs[36][tid] = row[DIMc];
    }
    __syncthreads();

    for (int p = tid; p < 36 * 37; p += 128) {
        const int mq = p / 37, mk = p % 37;
        float acc = 0.0f;
        #pragma unroll
        for (int d = 0; d < 32; d++) acc = fmaf(qs[mq][d], ks[mk][d], acc);
        int d0, d1;
        if (mk == 36) { d0 = mq % 6; d1 = mq / 6; }
        else          { d0 = mq % 6 - mk % 6; d1 = mq / 6 - mk / 6; }
        const int idx = (d0 + 5) * 11 + (d1 + 5);
        sc[mq][mk] = acc + table[idx * NHc + h];
    }
    __syncthreads();

    if (tid < 36) {
        float mx = -1e30f;
        #pragma unroll
        for (int k = 0; k < 37; k++) mx = fmaxf(mx, sc[tid][k]);
        float sum = 0.0f;
        #pragma unroll
        for (int k = 0; k < 37; k++) { const float e = expf(sc[tid][k] - mx); sc[tid][k] = e; sum += e; }
        const float inv = 1.0f / sum;
        #pragma unroll
        for (int k = 0; k < 37; k++) sc[tid][k] *= inv;
    }
    __syncthreads();

    for (int idx = tid; idx < 36 * 32; idx += 128) {
        const int m = idx >> 5, d = idx & 31;
        float acc = 0.0f;
        #pragma unroll
        for (int k = 0; k < 37; k++) acc = fmaf(sc[m][k], vs[k][d], acc);
        const int r = m / 6, c = m % 6;
        const int l = (wr * 6 + r) * 48 + wc * 6 + c;
        const size_t o = (size_t)(b * Lc + l) * DIMc + h * 32 + d;
        x1[o] = xin[o] + acc;
    }
}

// ---------------- global-token attention: one block per (b, h) -------------
__global__ __launch_bounds__(256)
void glob_attn(const float* __restrict__ kvqavg, const __half* __restrict__ kvq,
               const float* __restrict__ xavg_in, float* __restrict__ xavg1)
{
    const int b = blockIdx.x, h = blockIdx.y;
    __shared__ float qsh[32];
    __shared__ float wgt[Lc];
    __shared__ float red[8];
    const int tid = threadIdx.x, lane = tid & 31, wn = tid >> 5;

    if (tid < 32) qsh[tid] = kvqavg[(size_t)b * NKVQ + 2 * DIMc + h * 32 + tid] * SCALEc;
    __syncthreads();

    float lmax = -1e30f;
    for (int k = tid; k < Lc; k += 256) {
        const __half2* kp = (const __half2*)(kvq + (size_t)(b * Lc + k) * NKVQ + h * 32);
        float acc = 0.0f;
        #pragma unroll
        for (int d2 = 0; d2 < 16; d2++) {
            const float2 kk = __half22float2(kp[d2]);
            acc = fmaf(qsh[d2*2+0], kk.x, acc);
            acc = fmaf(qsh[d2*2+1], kk.y, acc);
        }
        wgt[k] = acc;
        lmax = fmaxf(lmax, acc);
    }
    #pragma unroll
    for (int o = 16; o; o >>= 1) lmax = fmaxf(lmax, __shfl_xor_sync(0xffffffffu, lmax, o));
    if (lane == 0) red[wn] = lmax;
    __syncthreads();
    float gmax = red[0];
    #pragma unroll
    for (int i = 1; i < 8; i++) gmax = fmaxf(gmax, red[i]);
    __syncthreads();

    float lsum = 0.0f;
    for (int k = tid; k < Lc; k += 256) {
        const float e = expf(wgt[k] - gmax);
        wgt[k] = e;
        lsum += e;
    }
    #pragma unroll
    for (int o = 16; o; o >>= 1) lsum += __shfl_xor_sync(0xffffffffu, lsum, o);
    if (lane == 0) red[wn] = lsum;
    __syncthreads();
    float gsum = 0.0f;
    #pragma unroll
    for (int i = 0; i < 8; i++) gsum += red[i];
    const float inv = 1.0f / gsum;

    float acc[4] = {0.f, 0.f, 0.f, 0.f};
    for (int k = lane; k < Lc; k += 32) {
        const float wk = wgt[k];
        const __half2* vv = (const __half2*)(kvq + (size_t)(b * Lc + k) * NKVQ + DIMc + h * 32 + wn * 4);
        const float2 v0 = __half22float2(vv[0]);
        const float2 v1 = __half22float2(vv[1]);
        acc[0] = fmaf(wk, v0.x, acc[0]);
        acc[1] = fmaf(wk, v0.y, acc[1]);
        acc[2] = fmaf(wk, v1.x, acc[2]);
        acc[3] = fmaf(wk, v1.y, acc[3]);
    }
    #pragma unroll
    for (int j = 0; j < 4; j++) {
        #pragma unroll
        for (int o = 16; o; o >>= 1) acc[j] += __shfl_xor_sync(0xffffffffu, acc[j], o);
    }
    if (lane == 0) {
        #pragma unroll
        for (int j = 0; j < 4; j++) {
            const size_t o = (size_t)b * DIMc + h * 32 + wn * 4 + j;
            xavg1[o] = xavg_in[o] + acc[j] * inv;
        }
    }
}

// ---------------------------------------------------------------------------
extern "C" void kernel_launch(void* const* d_in, const int* in_sizes, int n_in,
                              void* d_out, int out_size)
{
    const float* x     = (const float*)d_in[0];
    const float* xavg  = (const float*)d_in[1];
    const float* w_kv  = (const float*)d_in[2];
    const float* b_kv  = (const float*)d_in[3];
    const float* w_q   = (const float*)d_in[4];
    const float* b_q   = (const float*)d_in[5];
    const float* table = (const float*)d_in[6];
    const float* g1    = (const float*)d_in[7];
    const float* be1   = (const float*)d_in[8];
    const float* g2    = (const float*)d_in[9];
    const float* be2   = (const float*)d_in[10];
    const float* w_fc1 = (const float*)d_in[11];
    const float* b_fc1 = (const float*)d_in[12];
    const float* w_fc2 = (const float*)d_in[13];
    const float* b_fc2 = (const float*)d_in[14];
    float* out = (float*)d_out;

    __half *xnh, *kvqh, *hbuf, *wkvqT, *wfc1T, *wfc2T;
    float *x1, *kvqavg, *xavgn, *xavg1, *havg, *bkvq;
    cudaGetSymbolAddress((void**)&xnh,    g_xnh);
    cudaGetSymbolAddress((void**)&kvqh,   g_kvqh);
    cudaGetSymbolAddress((void**)&x1,     g_x1);
    cudaGetSymbolAddress((void**)&hbuf,   g_h);
    cudaGetSymbolAddress((void**)&kvqavg, g_kvqavg);
    cudaGetSymbolAddress((void**)&xavgn,  g_xavgn);
    cudaGetSymbolAddress((void**)&xavg1,  g_xavg1);
    cudaGetSymbolAddress((void**)&havg,   g_havg);
    cudaGetSymbolAddress((void**)&wkvqT,  g_wkvqT);
    cudaGetSymbolAddress((void**)&bkvq,   g_bkvq);
    cudaGetSymbolAddress((void**)&wfc1T,  g_wfc1T);
    cudaGetSymbolAddress((void**)&wfc2T,  g_wfc2T);

    // dynamic smem: 4 stages x (128+256) rows x 40 halfs x 2B = 122880 B
    const int SMEM_SZ = 4 * (128 + 256) * 40 * 2;
    cudaFuncSetAttribute(hgemm<0, false, true >, cudaFuncAttributeMaxDynamicSharedMemorySize, SMEM_SZ);
    cudaFuncSetAttribute(hgemm<1, false, true >, cudaFuncAttributeMaxDynamicSharedMemorySize, SMEM_SZ);
    cudaFuncSetAttribute(hgemm<0, true,  false>, cudaFuncAttributeMaxDynamicSharedMemorySize, SMEM_SZ);

    // 0. weight prep: transpose to [N,K] + fp16; fuse kv|q bias
    transpose_half<<<dim3(1024/32, 512/32),  dim3(32, 8)>>>(w_kv,  wkvqT,              512, 1024);
    transpose_half<<<dim3( 512/32, 512/32),  dim3(32, 8)>>>(w_q,   wkvqT + 1024 * 512, 512,  512);
    transpose_half<<<dim3(2048/32, 512/32),  dim3(32, 8)>>>(w_fc1, wfc1T,              512, 2048);
    transpose_half<<<dim3( 512/32, 2048/32), dim3(32, 8)>>>(w_fc2, wfc2T,             2048,  512);
    fuse_bias<<<6, 256>>>(b_kv, b_q, bkvq);

    // 1. LayerNorm 1
    ln_kernel_h<<<NTOK, 128>>>(x,    g1, be1, xnh);
    ln_kernel_f<<<Bc,   128>>>(xavg, g1, be1, xavgn);

    // 2. Fused kvq projection (fp16 tensor cores, half output)
    hgemm<0, false, true><<<dim3(NKVQ/256, NTOK/128), 256, SMEM_SZ>>>(NTOK, NKVQ, DIMc, xnh, wkvqT, bkvq, nullptr, kvqh);
    small_gemm<0, false><<<dim3(1024/128, Bc), 128>>>(1024, DIMc, NKVQ, xavgn, w_kv, b_kv, nullptr, kvqavg);
    small_gemm<0, false><<<dim3( 512/128, Bc), 128>>>( 512, DIMc, NKVQ, xavgn, w_q,  b_q,  nullptr, kvqavg + 2 * DIMc);

    // 3. Attention (+ residual)
    win_attn <<<dim3(Bc*NWc, NHc), 128>>>(kvqh, kvqavg, table, x, x1);
    glob_attn<<<dim3(Bc,     NHc), 256>>>(kvqavg, kvqh, xavg, xavg1);

    // 4. LayerNorm 2
    ln_kernel_h<<<NTOK, 128>>>(x1,    g2, be2, xnh);
    ln_kernel_f<<<Bc,   128>>>(xavg1, g2, be2, xavgn);

    // 5. MLP (+ residual), final outputs
    hgemm<1, false, true ><<<dim3(HID/256,  NTOK/128), 256, SMEM_SZ>>>(NTOK, HID,  DIMc, xnh,  wfc1T, b_fc1, nullptr, hbuf);
    hgemm<0, true,  false><<<dim3(DIMc/256, NTOK/128), 256, SMEM_SZ>>>(NTOK, DIMc, HID,  hbuf, wfc2T, b_fc2, x1, out);
    small_gemm<1, false><<<dim3(HID/128,  Bc), 128>>>(HID,  DIMc, HID,  xavgn, w_fc1, b_fc1, nullptr, havg);
    small_gemm<0, true ><<<dim3(DIMc/128, Bc), 128>>>(DIMc, HID,  DIMc, havg,  w_fc2, b_fc2, xavg1, out + (size_t)NTOK * DIMc);
}

// round 10
// speedup vs baseline: 1.5134x; 1.5134x over previous
#include <cuda_runtime.h>
#include <cuda_fp16.h>
#include <math.h>
#include <stdint.h>

// Problem constants
#define Bc   16
#define NHc  16
#define DIMc 512
#define Lc   2304          // 48*48
#define NWc  64            // (48/6)^2
#define HID  2048          // 4*DIM
#define SCALEc 0.17677669529663689f   // 32^-0.5
#define NTOK (Bc*Lc)       // 36864
#define NKVQ 1536          // fused kv(1024) + q(512)
#define MPAD (NTOK + 128)  // 36992: +16 global tokens, padded to tile
#define NVALID (NTOK + 16) // rows that may be written to d_out

// ---------------- scratch (device globals; no allocation allowed) ----------
// rows 0..NTOK-1: image tokens; rows NTOK..NTOK+15: global tokens;
// rows NTOK+16..MPAD-1: padding (never written; zero-initialized)
__device__ __half g_xnh [MPAD * DIMc];
__device__ __half g_kvqh[MPAD * NKVQ];
__device__ float  g_x1  [MPAD * DIMc];
__device__ __half g_h   [MPAD * HID];
// transposed ([N,K] row-major) fp16 weights
__device__ __half g_wkvqT[NKVQ * DIMc];
__device__ float  g_bkvq [NKVQ];
__device__ __half g_wfc1T[HID * DIMc];
__device__ __half g_wfc2T[DIMc * HID];

__device__ __forceinline__ float gelu_exact(float v) {
    return 0.5f * v * (1.0f + erff(v * 0.70710678118654752440f));
}

#define CP16(dst, src) \
    asm volatile("cp.async.cg.shared.global [%0], [%1], 16;\n" :: "r"(dst), "l"(src))
#define CPCOMMIT() asm volatile("cp.async.commit_group;\n")
#define LDSM4(r0, r1, r2, r3, addr) \
    asm volatile("ldmatrix.sync.aligned.m8n8.x4.shared.b16 {%0,%1,%2,%3}, [%4];" \
                 : "=r"(r0), "=r"(r1), "=r"(r2), "=r"(r3) : "r"(addr))

// ---------------- weight prep: tiled transpose + fp16 convert --------------
__global__ __launch_bounds__(256)
void transpose_half(const float* __restrict__ src, __half* __restrict__ dst,
                    int K, int N)
{
    __shared__ float tile[32][33];
    const int kb = blockIdx.y * 32, nb = blockIdx.x * 32;
    const int tx = threadIdx.x, ty = threadIdx.y;
    #pragma unroll
    for (int i = ty; i < 32; i += 8)
        tile[i][tx] = src[(size_t)(kb + i) * N + nb + tx];
    __syncthreads();
    #pragma unroll
    for (int i = ty; i < 32; i += 8)
        dst[(size_t)(nb + i) * K + kb + tx] = __float2half_rn(tile[tx][i]);
}

__global__ void fuse_bias(const float* __restrict__ b_kv, const float* __restrict__ b_q,
                          float* __restrict__ bkvq)
{
    const int i = blockIdx.x * blockDim.x + threadIdx.x;
    if (i < NKVQ) bkvq[i] = (i < 2 * DIMc) ? b_kv[i] : b_q[i - 2 * DIMc];
}

// ---------------- LayerNorm over DIM=512, one block per token --------------
__global__ __launch_bounds__(128)
void ln_kernel_h(const float* __restrict__ x, const float* __restrict__ g,
                 const float* __restrict__ be, __half* __restrict__ y)
{
    __shared__ float sS[4], sQ[4];
    const int t = blockIdx.x;
    const int tid = threadIdx.x;
    const float4 v = ((const float4*)(x + (size_t)t * DIMc))[tid];
    float s = v.x + v.y + v.z + v.w;
    float q = v.x*v.x + v.y*v.y + v.z*v.z + v.w*v.w;
    #pragma unroll
    for (int o = 16; o; o >>= 1) {
        s += __shfl_xor_sync(0xffffffffu, s, o);
        q += __shfl_xor_sync(0xffffffffu, q, o);
    }
    if ((tid & 31) == 0) { sS[tid >> 5] = s; sQ[tid >> 5] = q; }
    __syncthreads();
    const float S = sS[0] + sS[1] + sS[2] + sS[3];
    const float Q = sQ[0] + sQ[1] + sQ[2] + sQ[3];
    const float mean = S * (1.0f / 512.0f);
    const float var  = Q * (1.0f / 512.0f) - mean * mean;
    const float rstd = rsqrtf(var + 1e-3f);
    const float4 gg = ((const float4*)g)[tid];
    const float4 bb = ((const float4*)be)[tid];
    __half2 h0 = __floats2half2_rn((v.x - mean) * rstd * gg.x + bb.x,
                                   (v.y - mean) * rstd * gg.y + bb.y);
    __half2 h1 = __floats2half2_rn((v.z - mean) * rstd * gg.z + bb.z,
                                   (v.w - mean) * rstd * gg.w + bb.w);
    __half2* yp = (__half2*)(y + (size_t)t * DIMc);
    yp[tid * 2 + 0] = h0;
    yp[tid * 2 + 1] = h1;
}

// ---------------- fp16 tensor-core GEMM: 128x128 tile, 4-stage pipeline ----
// C[M,N] = act(A[M,K]h @ WT[N,K]h^T + bias)(+R). 256 threads, 2x4 warps of
// 64x32, mma.m16n8k16.f16.f32, LDSM fragments. Rows >= Mv are computed but
// not stored (M padding for the fused global-token path).
template<int ACT, bool RES, bool OUTH>
__global__ __launch_bounds__(256, 2)
void hgemm(int M, int N, int K, int Mv,
           const __half* __restrict__ A, const __half* __restrict__ WT,
           const float* __restrict__ bias, const float* __restrict__ R,
           void* __restrict__ Cv)
{
    constexpr int BM = 128, BN = 128, BK = 32;   // BK in halfs
    constexpr int PAD = 40;                       // halfs per smem row
    constexpr int STG = 4;
    constexpr uint32_t A_BYTES  = (uint32_t)BM * PAD * 2u;          // 10240
    constexpr uint32_t ST_BYTES = (uint32_t)(BM + BN) * PAD * 2u;   // 20480

    extern __shared__ __align__(16) __half smem[];

    const int tid  = threadIdx.x;
    const int lane = tid & 31;
    const int warp = tid >> 5;
    const int wm   = warp >> 2;          // 0..1
    const int wn   = warp & 3;           // 0..3
    const int bm   = blockIdx.y * BM;
    const int bn   = blockIdx.x * BN;

    const uint32_t sb = (uint32_t)__cvta_generic_to_shared(smem);

    // loaders: each tile is 128 rows x 64 bytes; thread: row=tid>>1, 32B half
    const int l_r = tid >> 1;
    const int l_o = (tid & 1) << 4;      // half offset 0 or 16
    const __half* a_src = A  + (size_t)(bm + l_r) * K + l_o;
    const __half* b_src = WT + (size_t)(bn + l_r) * K + l_o;
    const uint32_t a_dst = sb + (uint32_t)(l_r * PAD + l_o) * 2u;
    const uint32_t b_dst = sb + A_BYTES + (uint32_t)(l_r * PAD + l_o) * 2u;

    // ldmatrix base addresses (stage 0)
    uint32_t aLd[4];
    #pragma unroll
    for (int mt = 0; mt < 4; mt++) {
        const int row = wm * 64 + mt * 16 + (lane & 15);
        const int col = (lane >> 4) * 8;
        aLd[mt] = sb + (uint32_t)(row * PAD + col) * 2u;
    }
    uint32_t bLd[2];
    #pragma unroll
    for (int ng = 0; ng < 2; ng++) {
        const int row = wn * 32 + ng * 16 + (lane & 7) + (lane >> 4) * 8;
        const int col = ((lane >> 3) & 1) * 8;
        bLd[ng] = sb + A_BYTES + (uint32_t)(row * PAD + col) * 2u;
    }

    float acc[4][4][4] = {};
    const int T = K / BK;

    // prologue: stages 0..2
    #pragma unroll
    for (int s = 0; s < STG - 1; s++) {
        const uint32_t o = (uint32_t)s * ST_BYTES;
        const int k0 = s * BK;
        CP16(a_dst + o, a_src + k0); CP16(a_dst + o + 16u, a_src + k0 + 8);
        CP16(b_dst + o, b_src + k0); CP16(b_dst + o + 16u, b_src + k0 + 8);
        CPCOMMIT();
    }

    for (int t = 0; t < T; t++) {
        asm volatile("cp.async.wait_group 2;\n");
        __syncthreads();

        if (t + STG - 1 < T) {
            const int k0 = (t + STG - 1) * BK;
            const uint32_t o = (uint32_t)((t + STG - 1) % STG) * ST_BYTES;
            CP16(a_dst + o, a_src + k0); CP16(a_dst + o + 16u, a_src + k0 + 8);
            CP16(b_dst + o, b_src + k0); CP16(b_dst + o + 16u, b_src + k0 + 8);
        }
        CPCOMMIT();

        const uint32_t so = (uint32_t)(t % STG) * ST_BYTES;

        #pragma unroll
        for (int ks = 0; ks < BK; ks += 16) {
            uint32_t af[4][4];
            #pragma unroll
            for (int mt = 0; mt < 4; mt++)
                LDSM4(af[mt][0], af[mt][1], af[mt][2], af[mt][3],
                      aLd[mt] + so + (uint32_t)ks * 2u);
            uint32_t bf[4][2];
            #pragma unroll
            for (int ng = 0; ng < 2; ng++)
                LDSM4(bf[2*ng][0], bf[2*ng][1], bf[2*ng+1][0], bf[2*ng+1][1],
                      bLd[ng] + so + (uint32_t)ks * 2u);
            #pragma unroll
            for (int mt = 0; mt < 4; mt++)
                #pragma unroll
                for (int nt = 0; nt < 4; nt++)
                    asm volatile(
                        "mma.sync.aligned.m16n8k16.row.col.f32.f16.f16.f32 "
                        "{%0,%1,%2,%3}, {%4,%5,%6,%7}, {%8,%9}, {%0,%1,%2,%3};\n"
                        : "+f"(acc[mt][nt][0]), "+f"(acc[mt][nt][1]),
                          "+f"(acc[mt][nt][2]), "+f"(acc[mt][nt][3])
                        : "r"(af[mt][0]), "r"(af[mt][1]), "r"(af[mt][2]), "r"(af[mt][3]),
                          "r"(bf[nt][0]), "r"(bf[nt][1]));
        }
    }

    // ---- epilogue (stores guarded by Mv) ----
    float* Cf = (float*)Cv;
    __half* Ch = (__half*)Cv;
    #pragma unroll
    for (int mt = 0; mt < 4; mt++) {
        #pragma unroll
        for (int nt = 0; nt < 4; nt++) {
            const int r0 = bm + wm * 64 + mt * 16 + (lane >> 2);
            const int c  = bn + wn * 32 + nt * 8 + (lane & 3) * 2;
            const float bx = bias[c], by = bias[c + 1];
            #pragma unroll
            for (int half_ = 0; half_ < 2; half_++) {
                const int r = r0 + half_ * 8;
                if (r >= Mv) continue;
                float vx = acc[mt][nt][half_ * 2 + 0] + bx;
                float vy = acc[mt][nt][half_ * 2 + 1] + by;
                if (ACT == 1) { vx = gelu_exact(vx); vy = gelu_exact(vy); }
                if (RES) {
                    const float2 rr = *(const float2*)(R + (size_t)r * N + c);
                    vx += rr.x; vy += rr.y;
                }
                if (OUTH) {
                    *(__half2*)(Ch + (size_t)r * N + c) = __floats2half2_rn(vx, vy);
                } else {
                    float2 o; o.x = vx; o.y = vy;
                    *(float2*)(Cf + (size_t)r * N + c) = o;
                }
            }
        }
    }
}

// ---------------- window attention: one block per (window, head) -----------
__global__ __launch_bounds__(128)
void win_attn(const __half* __restrict__ kvq, const float* __restrict__ table,
              const float* __restrict__ xin, float* __restrict__ x1)
{
    const int w = blockIdx.x;            // 0..1023
    const int h = blockIdx.y;            // 0..15
    const int b  = w >> 6;
    const int wi = w & 63;
    const int wr = wi >> 3, wc = wi & 7;

    __shared__ float qs[36][33];
    __shared__ float ks[37][33];
    __shared__ float vs[37][33];
    __shared__ float sc[36][37];

    const int tid = threadIdx.x;

    for (int idx = tid; idx < 36 * 32; idx += 128) {
        const int m = idx >> 5, d = idx & 31;
        const int r = m / 6, c = m % 6;
        const int l = (wr * 6 + r) * 48 + wc * 6 + c;
        const __half* row = kvq + (size_t)(b * Lc + l) * NKVQ + h * 32 + d;
        ks[m][d] = __half2float(row[0]);
        vs[m][d] = __half2float(row[DIMc]);
        qs[m][d] = __half2float(row[2 * DIMc]) * SCALEc;
    }
    if (tid < 32) {
        // global-token kv lives at row NTOK + b of the fused kvq buffer
        const __half* row = kvq + (size_t)(NTOK + b) * NKVQ + h * 32 + tid;
        ks[36][tid] = __half2float(row[0]);
        vs[36][tid] = __half2float(row[DIMc]);
    }
    __syncthreads();

    for (int p = tid; p < 36 * 37; p += 128) {
        const int mq = p / 37, mk = p % 37;
        float acc = 0.0f;
        #pragma unroll
        for (int d = 0; d < 32; d++) acc = fmaf(qs[mq][d], ks[mk][d], acc);
        int d0, d1;
        if (mk == 36) { d0 = mq % 6; d1 = mq / 6; }
        else          { d0 = mq % 6 - mk % 6; d1 = mq / 6 - mk / 6; }
        const int idx = (d0 + 5) * 11 + (d1 + 5);
        sc[mq][mk] = acc + table[idx * NHc + h];
    }
    __syncthreads();

    if (tid < 36) {
        float mx = -1e30f;
        #pragma unroll
        for (int k = 0; k < 37; k++) mx = fmaxf(mx, sc[tid][k]);
        float sum = 0.0f;
        #pragma unroll
        for (int k = 0; k < 37; k++) { const float e = expf(sc[tid][k] - mx); sc[tid][k] = e; sum += e; }
        const float inv = 1.0f / sum;
        #pragma unroll
        for (int k = 0; k < 37; k++) sc[tid][k] *= inv;
    }
    __syncthreads();

    for (int idx = tid; idx < 36 * 32; idx += 128) {
        const int m = idx >> 5, d = idx & 31;
        float acc = 0.0f;
        #pragma unroll
        for (int k = 0; k < 37; k++) acc = fmaf(sc[m][k], vs[k][d], acc);
        const int r = m / 6, c = m % 6;
        const int l = (wr * 6 + r) * 48 + wc * 6 + c;
        const size_t o = (size_t)(b * Lc + l) * DIMc + h * 32 + d;
        x1[o] = xin[o] + acc;
    }
}

// ---------------- global-token attention: one block per (b, h) -------------
// writes x1 row NTOK + b (residual from xavg input)
__global__ __launch_bounds__(256)
void glob_attn(const __half* __restrict__ kvq,
               const float* __restrict__ xavg_in, float* __restrict__ x1)
{
    const int b = blockIdx.x, h = blockIdx.y;
    __shared__ float qsh[32];
    __shared__ float wgt[Lc];
    __shared__ float red[8];
    const int tid = threadIdx.x, lane = tid & 31, wn = tid >> 5;

    if (tid < 32)
        qsh[tid] = __half2float(kvq[(size_t)(NTOK + b) * NKVQ + 2 * DIMc + h * 32 + tid]) * SCALEc;
    __syncthreads();

    float lmax = -1e30f;
    for (int k = tid; k < Lc; k += 256) {
        const __half2* kp = (const __half2*)(kvq + (size_t)(b * Lc + k) * NKVQ + h * 32);
        float acc = 0.0f;
        #pragma unroll
        for (int d2 = 0; d2 < 16; d2++) {
            const float2 kk = __half22float2(kp[d2]);
            acc = fmaf(qsh[d2*2+0], kk.x, acc);
            acc = fmaf(qsh[d2*2+1], kk.y, acc);
        }
        wgt[k] = acc;
        lmax = fmaxf(lmax, acc);
    }
    #pragma unroll
    for (int o = 16; o; o >>= 1) lmax = fmaxf(lmax, __shfl_xor_sync(0xffffffffu, lmax, o));
    if (lane == 0) red[wn] = lmax;
    __syncthreads();
    float gmax = red[0];
    #pragma unroll
    for (int i = 1; i < 8; i++) gmax = fmaxf(gmax, red[i]);
    __syncthreads();

    float lsum = 0.0f;
    for (int k = tid; k < Lc; k += 256) {
        const float e = expf(wgt[k] - gmax);
        wgt[k] = e;
        lsum += e;
    }
    #pragma unroll
    for (int o = 16; o; o >>= 1) lsum += __shfl_xor_sync(0xffffffffu, lsum, o);
    if (lane == 0) red[wn] = lsum;
    __syncthreads();
    float gsum = 0.0f;
    #pragma unroll
    for (int i = 0; i < 8; i++) gsum += red[i];
    const float inv = 1.0f / gsum;

    float acc[4] = {0.f, 0.f, 0.f, 0.f};
    for (int k = lane; k < Lc; k += 32) {
        const float wk = wgt[k];
        const __half2* vv = (const __half2*)(kvq + (size_t)(b * Lc + k) * NKVQ + DIMc + h * 32 + wn * 4);
        const float2 v0 = __half22float2(vv[0]);
        const float2 v1 = __half22float2(vv[1]);
        acc[0] = fmaf(wk, v0.x, acc[0]);
        acc[1] = fmaf(wk, v0.y, acc[1]);
        acc[2] = fmaf(wk, v1.x, acc[2]);
        acc[3] = fmaf(wk, v1.y, acc[3]);
    }
    #pragma unroll
    for (int j = 0; j < 4; j++) {
        #pragma unroll
        for (int o = 16; o; o >>= 1) acc[j] += __shfl_xor_sync(0xffffffffu, acc[j], o);
    }
    if (lane == 0) {
        #pragma unroll
        for (int j = 0; j < 4; j++) {
            const int c = h * 32 + wn * 4 + j;
            x1[(size_t)(NTOK + b) * DIMc + c] = xavg_in[(size_t)b * DIMc + c] + acc[j] * inv;
        }
    }
}

// ---------------------------------------------------------------------------
extern "C" void kernel_launch(void* const* d_in, const int* in_sizes, int n_in,
                              void* d_out, int out_size)
{
    const float* x     = (const float*)d_in[0];
    const float* xavg  = (const float*)d_in[1];
    const float* w_kv  = (const float*)d_in[2];
    const float* b_kv  = (const float*)d_in[3];
    const float* w_q   = (const float*)d_in[4];
    const float* b_q   = (const float*)d_in[5];
    const float* table = (const float*)d_in[6];
    const float* g1    = (const float*)d_in[7];
    const float* be1   = (const float*)d_in[8];
    const float* g2    = (const float*)d_in[9];
    const float* be2   = (const float*)d_in[10];
    const float* w_fc1 = (const float*)d_in[11];
    const float* b_fc1 = (const float*)d_in[12];
    const float* w_fc2 = (const float*)d_in[13];
    const float* b_fc2 = (const float*)d_in[14];
    float* out = (float*)d_out;

    __half *xnh, *kvqh, *hbuf, *wkvqT, *wfc1T, *wfc2T;
    float *x1, *bkvq;
    cudaGetSymbolAddress((void**)&xnh,    g_xnh);
    cudaGetSymbolAddress((void**)&kvqh,   g_kvqh);
    cudaGetSymbolAddress((void**)&x1,     g_x1);
    cudaGetSymbolAddress((void**)&hbuf,   g_h);
    cudaGetSymbolAddress((void**)&wkvqT,  g_wkvqT);
    cudaGetSymbolAddress((void**)&bkvq,   g_bkvq);
    cudaGetSymbolAddress((void**)&wfc1T,  g_wfc1T);
    cudaGetSymbolAddress((void**)&wfc2T,  g_wfc2T);

    // dynamic smem: 4 stages x 256 rows x 40 halfs x 2B = 81920 B
    const int SMEM_SZ = 4 * 256 * 40 * 2;
    cudaFuncSetAttribute(hgemm<0, false, true >, cudaFuncAttributeMaxDynamicSharedMemorySize, SMEM_SZ);
    cudaFuncSetAttribute(hgemm<1, false, true >, cudaFuncAttributeMaxDynamicSharedMemorySize, SMEM_SZ);
    cudaFuncSetAttribute(hgemm<0, true,  false>, cudaFuncAttributeMaxDynamicSharedMemorySize, SMEM_SZ);

    // 0. weight prep: transpose to [N,K] + fp16; fuse kv|q bias
    transpose_half<<<dim3(1024/32, 512/32),  dim3(32, 8)>>>(w_kv,  wkvqT,              512, 1024);
    transpose_half<<<dim3( 512/32, 512/32),  dim3(32, 8)>>>(w_q,   wkvqT + 1024 * 512, 512,  512);
    transpose_half<<<dim3(2048/32, 512/32),  dim3(32, 8)>>>(w_fc1, wfc1T,              512, 2048);
    transpose_half<<<dim3( 512/32, 2048/32), dim3(32, 8)>>>(w_fc2, wfc2T,             2048,  512);
    fuse_bias<<<6, 256>>>(b_kv, b_q, bkvq);

    // 1. LayerNorm 1 (image tokens -> rows 0..NTOK-1; global -> NTOK..NTOK+15)
    ln_kernel_h<<<NTOK, 128>>>(x,    g1, be1, xnh);
    ln_kernel_h<<<Bc,   128>>>(xavg, g1, be1, xnh + (size_t)NTOK * DIMc);

    // 2. Fused kvq projection over ALL tokens (image + global) in one GEMM
    hgemm<0, false, true><<<dim3(NKVQ/128, MPAD/128), 256, SMEM_SZ>>>(
        MPAD, NKVQ, DIMc, MPAD, xnh, wkvqT, bkvq, nullptr, kvqh);

    // 3. Attention (+ residual); glob_attn writes x1 row NTOK+b
    win_attn <<<dim3(Bc*NWc, NHc), 128>>>(kvqh, table, x, x1);
    glob_attn<<<dim3(Bc,     NHc), 256>>>(kvqh, xavg, x1);

    // 4. LayerNorm 2 (both paths, same fused layout)
    ln_kernel_h<<<NTOK, 128>>>(x1, g2, be2, xnh);
    ln_kernel_h<<<Bc,   128>>>(x1 + (size_t)NTOK * DIMc, g2, be2, xnh + (size_t)NTOK * DIMc);

    // 5. MLP (+ residual) over ALL tokens; fc2 stores only rows < NTOK+16
    hgemm<1, false, true ><<<dim3(HID/128,  MPAD/128), 256, SMEM_SZ>>>(
        MPAD, HID,  DIMc, MPAD,   xnh,  wfc1T, b_fc1, nullptr, hbuf);
    hgemm<0, true,  false><<<dim3(DIMc/128, MPAD/128), 256, SMEM_SZ>>>(
        MPAD, DIMc, HID,  NVALID, hbuf, wfc2T, b_fc2, x1, out);
}